// round 15
// baseline (speedup 1.0000x reference)
#include <cuda_runtime.h>
#include <cuda_fp16.h>
#include <math.h>
#include <stdint.h>

#define BB 64
#define NN 256
#define DD 64
#define TT 4096
#define T_TILE 128
#define TCH (TT / T_TILE)          // 32
#define THREADS 128
#define WARPS 4
#define NSLAB 32
#define SLABS (NN / NSLAB)         // 8
#define KREC 128                   // records per (b,n): 32 tc x 4 warps

#define DATA_ELTS (BB * NN * DD)   // 1048576
#define W_ELTS (TT * DD)           // 262144

// fp16 limb arrays (hi, mid), row-major d-contiguous
__device__ __align__(16) __half g_dlimb[2][DATA_ELTS];
__device__ __align__(16) __half g_wlimb[2][W_ELTS];
// per-(b, n, k) LSE records: (lse, r). 16 MB, k-contiguous for merge.
__device__ float2 g_rec[(size_t)BB * NN * KREC];

// ---- smem layout (per CTA, 66 KB -> 3 CTAs/SM) ----
// [0, 32768):  W limbs during prologue (limb0 @0, limb1 @16384).
//              After afrag load: slab double buffers at [0,8192) and
//              [8192,16384) (each: limb0 +0, limb1 +4096).
#define SM_Z   32768                   // 32 x 132 floats (16896 B)
#define ZSTR   132
#define SM_CV  49664                   // 32 x 132 floats
#define SM_TGT 66560                   // 256 f32
#define SMEM_BYTES 67584

static __device__ __forceinline__ uint32_t smem_u32(const void* p) {
    uint32_t a;
    asm("{ .reg .u64 t; cvta.to.shared.u64 t, %1; cvt.u32.u64 %0, t; }"
        : "=r"(a) : "l"(p));
    return a;
}
static __device__ __forceinline__ void cp16(uint32_t dst, const void* src) {
    asm volatile("cp.async.cg.shared.global [%0], [%1], 16;" :: "r"(dst), "l"(src));
}
#define CP_COMMIT() asm volatile("cp.async.commit_group;")
#define CP_WAIT0()  asm volatile("cp.async.wait_group 0;" ::: "memory")
#define CP_WAIT1()  asm volatile("cp.async.wait_group 1;" ::: "memory")

static __device__ __forceinline__ void ldsm4(uint32_t a, uint32_t r[4]) {
    asm volatile("ldmatrix.sync.aligned.m8n8.x4.shared.b16 {%0,%1,%2,%3}, [%4];"
                 : "=r"(r[0]), "=r"(r[1]), "=r"(r[2]), "=r"(r[3]) : "r"(a));
}
static __device__ __forceinline__ void mma_f32(
    float d[4], const uint32_t a[4], uint32_t b0, uint32_t b1) {
    asm volatile(
        "mma.sync.aligned.m16n8k16.row.col.f32.f16.f16.f32 "
        "{%0,%1,%2,%3}, {%4,%5,%6,%7}, {%8,%9}, {%0,%1,%2,%3};"
        : "+f"(d[0]), "+f"(d[1]), "+f"(d[2]), "+f"(d[3])
        : "r"(a[0]), "r"(a[1]), "r"(a[2]), "r"(a[3]), "r"(b0), "r"(b1));
}
static __device__ __forceinline__ void mma_f16(
    uint32_t d[2], const uint32_t a[4], uint32_t b0, uint32_t b1) {
    asm volatile(
        "mma.sync.aligned.m16n8k16.row.col.f16.f16.f16.f16 "
        "{%0,%1}, {%2,%3,%4,%5}, {%6,%7}, {%0,%1};"
        : "+r"(d[0]), "+r"(d[1])
        : "r"(a[0]), "r"(a[1]), "r"(a[2]), "r"(a[3]), "r"(b0), "r"(b1));
}

// ---------------------------------------------------------------------------
// Prep: fp32 -> 2 fp16 limbs (hi/mid), 16 elements per thread (MLP=4).
// ---------------------------------------------------------------------------
__global__ void __launch_bounds__(256)
prep_kernel(const float* __restrict__ data, const float* __restrict__ W)
{
    size_t i = ((size_t)blockIdx.x * 256 + threadIdx.x) * 16;
    const bool isW = (i >= DATA_ELTS);
    size_t j = isW ? i - DATA_ELTS : i;
    const float* src = isW ? (W + j) : (data + j);

    float4 x[4];
    #pragma unroll
    for (int q = 0; q < 4; q++) x[q] = *(const float4*)(src + 4 * q);

    uint32_t hp[8], mp[8];
    #pragma unroll
    for (int q = 0; q < 4; q++) {
        float v[4] = {x[q].x, x[q].y, x[q].z, x[q].w};
        #pragma unroll
        for (int e = 0; e < 2; e++) {
            __half h0 = __float2half_rn(v[2*e]);
            __half h1 = __float2half_rn(v[2*e+1]);
            __half m0 = __float2half_rn(v[2*e]   - __half2float(h0));
            __half m1 = __float2half_rn(v[2*e+1] - __half2float(h1));
            __half2 hh = __halves2half2(h0, h1);
            __half2 mm = __halves2half2(m0, m1);
            hp[2*q+e] = *(uint32_t*)&hh;
            mp[2*q+e] = *(uint32_t*)&mm;
        }
    }
    __half* dh = isW ? &g_wlimb[0][j] : &g_dlimb[0][j];
    __half* dm = isW ? &g_wlimb[1][j] : &g_dlimb[1][j];
    *(uint4*)(dh)     = make_uint4(hp[0], hp[1], hp[2], hp[3]);
    *(uint4*)(dh + 8) = make_uint4(hp[4], hp[5], hp[6], hp[7]);
    *(uint4*)(dm)     = make_uint4(mp[0], mp[1], mp[2], mp[3]);
    *(uint4*)(dm + 8) = make_uint4(mp[4], mp[5], mp[6], mp[7]);
}

// ---------------------------------------------------------------------------
// Main: 3 CTAs/SM (66 KB smem), per-slab double buffers in dead W region,
// fp16 limbs: hh (f32 acc) + hm + mh (f16 acc). grid (TCH, BB), 128 threads.
// ---------------------------------------------------------------------------
extern "C" __global__ void __launch_bounds__(THREADS, 3)
main_kernel(const float* __restrict__ targets)
{
    extern __shared__ __align__(1024) char smem[];
    const uint32_t sb = smem_u32(smem);
    const int tc   = blockIdx.x;
    const int b    = blockIdx.y;
    const int tid  = threadIdx.x;
    const int w    = tid >> 5;
    const int lane = tid & 31;

    const __half* dbase0 = &g_dlimb[0][(size_t)b * NN * DD];
    const __half* dbase1 = &g_dlimb[1][(size_t)b * NN * DD];

    // ---- prologue A: W limbs (32 KB @0) + targets ----
    #pragma unroll
    for (int kq = 0; kq < 16; kq++) {
        int i = kq * THREADS + tid;
        int limb = i >> 10, rem = i & 1023, row = rem >> 3, c = rem & 7;
        cp16(sb + limb * 16384 + row * 128 + ((c ^ (row & 7)) << 4),
             &g_wlimb[limb][(size_t)(tc * T_TILE + row) * DD + c * 8]);
    }
    if (tid < 64) cp16(sb + SM_TGT + tid * 16, targets + (size_t)b * NN + tid * 4);
    CP_COMMIT();
    CP_WAIT0();
    __syncthreads();

    // fragment lane decomposition
    const int l7 = lane & 7;
    const int t1 = (lane >> 3) & 1;
    const int t2 = lane >> 4;

    uint32_t xA[4], xB[4];
    #pragma unroll
    for (int k = 0; k < 4; k++) {
        xA[k] = (uint32_t)(((2 * k + t2) ^ l7) << 4);
        xB[k] = (uint32_t)(((2 * k + t1) ^ l7) << 4);
    }

    // ---- load A fragments ONCE from the W region ----
    uint32_t afrag[2][4][2][4];               // [limb][k][half][4]
    {
        const uint32_t aRow = sb + (uint32_t)(32 * w + 8 * t1 + l7) * 128;
        #pragma unroll
        for (int limb = 0; limb < 2; limb++)
            #pragma unroll
            for (int k = 0; k < 4; k++) {
                const uint32_t aL = aRow + (uint32_t)limb * 16384;
                ldsm4(aL + xA[k],        afrag[limb][k][0]);
                ldsm4(aL + 2048 + xA[k], afrag[limb][k][1]);
            }
    }
    __syncthreads();                          // W region now dead -> buffers

    // ---- prologue B: slabs 0,1 into buffers 0,1 (inside W region) ----
    #pragma unroll
    for (int ss = 0; ss < 2; ss++) {
        #pragma unroll
        for (int kq = 0; kq < 4; kq++) {
            int i = kq * THREADS + tid;
            int limb = i >> 8, r2 = i & 255, row = r2 >> 3, c = r2 & 7;
            const __half* src = limb ? dbase1 : dbase0;
            cp16(sb + ss * 8192 + limb * 4096 + row * 128 + ((c ^ (row & 7)) << 4),
                 src + (size_t)(ss * NSLAB + row) * DD + c * 8);
        }
        CP_COMMIT();
    }
    CP_WAIT1();                               // slab 0 ready
    __syncthreads();

    float* zw  = (float*)(smem + SM_Z);
    float* cvw = (float*)(smem + SM_CV);
    const float* s_tgt = (const float*)(smem + SM_TGT);

    float cum = 0.f;
    const int gw = tc * WARPS + w;
    const uint32_t bOff = sb + (uint32_t)(8 * t2 + l7) * 128;

    const int r0 = lane >> 2;
    const int c0 = 2 * (lane & 3);

    for (int s = 0; s < SLABS; s++) {
        // ---- load B fragments for slab s from buffer s&1 ----
        uint32_t bfrag[2][4][2][4];
        const uint32_t bR = bOff + (uint32_t)((s & 1) * 8192);
        #pragma unroll
        for (int limb = 0; limb < 2; limb++)
            #pragma unroll
            for (int k = 0; k < 4; k++) {
                const uint32_t bL = bR + (uint32_t)limb * 4096;
                ldsm4(bL + xB[k],        bfrag[limb][k][0]);
                ldsm4(bL + 2048 + xB[k], bfrag[limb][k][1]);
            }
        __syncthreads();                      // buffer s&1 free

        // ---- stage slab s+2 into the freed buffer ----
        if (s + 2 < SLABS) {
            #pragma unroll
            for (int kq = 0; kq < 4; kq++) {
                int i = kq * THREADS + tid;
                int limb = i >> 8, r2 = i & 255, row = r2 >> 3, c = r2 & 7;
                const __half* src = limb ? dbase1 : dbase0;
                cp16(sb + (uint32_t)((s & 1) * 8192) + limb * 4096 +
                         row * 128 + ((c ^ (row & 7)) << 4),
                     src + (size_t)((s + 2) * NSLAB + row) * DD + c * 8);
            }
        }
        CP_COMMIT();

        // ---- GEMM: hh (f32 acc) + hm + mh (f16 acc) ----
        float acc[2][4][4];
        uint32_t accc[2][4][2];
        #pragma unroll
        for (int mt = 0; mt < 2; mt++)
            #pragma unroll
            for (int q = 0; q < 4; q++) {
                acc[mt][q][0] = acc[mt][q][1] = 0.f;
                acc[mt][q][2] = acc[mt][q][3] = 0.f;
                accc[mt][q][0] = 0u; accc[mt][q][1] = 0u;
            }

        #pragma unroll
        for (int k = 0; k < 4; k++) {
            const uint32_t* ah0 = afrag[0][k][0];
            const uint32_t* ah1 = afrag[0][k][1];
            const uint32_t* am0 = afrag[1][k][0];
            const uint32_t* am1 = afrag[1][k][1];
            const uint32_t* bh0 = bfrag[0][k][0];
            const uint32_t* bh1 = bfrag[0][k][1];
            const uint32_t* bm0 = bfrag[1][k][0];
            const uint32_t* bm1 = bfrag[1][k][1];

            mma_f32(acc[0][0], ah0, bh0[0], bh0[1]);
            mma_f32(acc[0][1], ah0, bh0[2], bh0[3]);
            mma_f32(acc[0][2], ah0, bh1[0], bh1[1]);
            mma_f32(acc[0][3], ah0, bh1[2], bh1[3]);
            mma_f32(acc[1][0], ah1, bh0[0], bh0[1]);
            mma_f32(acc[1][1], ah1, bh0[2], bh0[3]);
            mma_f32(acc[1][2], ah1, bh1[0], bh1[1]);
            mma_f32(acc[1][3], ah1, bh1[2], bh1[3]);

            mma_f16(accc[0][0], ah0, bm0[0], bm0[1]);
            mma_f16(accc[0][1], ah0, bm0[2], bm0[3]);
            mma_f16(accc[0][2], ah0, bm1[0], bm1[1]);
            mma_f16(accc[0][3], ah0, bm1[2], bm1[3]);
            mma_f16(accc[1][0], ah1, bm0[0], bm0[1]);
            mma_f16(accc[1][1], ah1, bm0[2], bm0[3]);
            mma_f16(accc[1][2], ah1, bm1[0], bm1[1]);
            mma_f16(accc[1][3], ah1, bm1[2], bm1[3]);

            mma_f16(accc[0][0], am0, bh0[0], bh0[1]);
            mma_f16(accc[0][1], am0, bh0[2], bh0[3]);
            mma_f16(accc[0][2], am0, bh1[0], bh1[1]);
            mma_f16(accc[0][3], am0, bh1[2], bh1[3]);
            mma_f16(accc[1][0], am1, bh0[0], bh0[1]);
            mma_f16(accc[1][1], am1, bh0[2], bh0[3]);
            mma_f16(accc[1][2], am1, bh1[0], bh1[1]);
            mma_f16(accc[1][3], am1, bh1[2], bh1[3]);
        }

        // ---- transpose-store z[n_local][t_local] with f16 corrections ----
        #pragma unroll
        for (int mt = 0; mt < 2; mt++) {
            const int tg = 32 * w + 16 * mt + r0;
            #pragma unroll
            for (int q = 0; q < 4; q++) {
                const int nl = 8 * q + c0;
                __half2 p0 = *reinterpret_cast<__half2*>(&accc[mt][q][0]);
                __half2 p1 = *reinterpret_cast<__half2*>(&accc[mt][q][1]);
                zw[nl * ZSTR + tg]           = acc[mt][q][0] + __low2float(p0);
                zw[(nl + 1) * ZSTR + tg]     = acc[mt][q][1] + __high2float(p0);
                zw[nl * ZSTR + tg + 8]       = acc[mt][q][2] + __low2float(p1);
                zw[(nl + 1) * ZSTR + tg + 8] = acc[mt][q][3] + __high2float(p1);
            }
        }
        __syncwarp();

        // ---- phase A: cumulative loglik scan (thread = task) ----
        #pragma unroll
        for (int j = 0; j < NSLAB; j++) {
            float z  = zw[j * ZSTR + tid];
            float tn = s_tgt[s * NSLAB + j];
            cvw[j * ZSTR + tid] = cum;
            float r = tn - z;
            cum = fmaf(-0.5f * r, r, cum);
        }
        __syncwarp();

        // ---- phase B (two-pass): per-n reduction over warp's 32 tasks ----
        {
            const float* cvr = cvw + lane * ZSTR + 32 * w;
            const float* zr  = zw  + lane * ZSTR + 32 * w;

            float m = -3.4e38f;
            #pragma unroll
            for (int k = 0; k < 8; k++) {
                float4 v = *(const float4*)(cvr + 4 * k);
                m = fmaxf(m, fmaxf(fmaxf(v.x, v.y), fmaxf(v.z, v.w)));
            }
            float S = 0.f, P = 0.f;
            #pragma unroll
            for (int k = 0; k < 8; k++) {
                float4 cv = *(const float4*)(cvr + 4 * k);
                float4 zv = *(const float4*)(zr  + 4 * k);
                float e0 = __expf(cv.x - m);
                float e1 = __expf(cv.y - m);
                float e2 = __expf(cv.z - m);
                float e3 = __expf(cv.w - m);
                S += (e0 + e1) + (e2 + e3);
                P = fmaf(e0, zv.x, P);
                P = fmaf(e1, zv.y, P);
                P = fmaf(e2, zv.z, P);
                P = fmaf(e3, zv.w, P);
            }
            const int n = s * NSLAB + lane;
            g_rec[((size_t)b * NN + n) * KREC + gw] =
                make_float2(m + __logf(S), __fdividef(P, S));
        }

        CP_WAIT1();                            // slab s+1 arrived
        __syncthreads();
    }
}

// ---------------------------------------------------------------------------
// Merge: 8 threads per (b,n), 16 LSE records each, coalesced k-major reads.
// n==0 falls out naturally (all partials uniform -> pred0).
// ---------------------------------------------------------------------------
extern "C" __global__ void __launch_bounds__(256)
merge_kernel(float* __restrict__ out)
{
    const int gp = blockIdx.x * 32 + (threadIdx.x >> 3);
    const int q  = threadIdx.x & 7;
    const int b  = gp >> 8;
    const int n  = gp & 255;
    const float2* base = &g_rec[((size_t)b * NN + n) * KREC];

    float2 rec[16];
    float M = -3.4e38f;
    #pragma unroll
    for (int i = 0; i < 16; i++) {
        rec[i] = __ldg(&base[i * 8 + q]);
        M = fmaxf(M, rec[i].x);
    }
    float gM = M;
    gM = fmaxf(gM, __shfl_xor_sync(0xffffffffu, gM, 1));
    gM = fmaxf(gM, __shfl_xor_sync(0xffffffffu, gM, 2));
    gM = fmaxf(gM, __shfl_xor_sync(0xffffffffu, gM, 4));

    float S = 0.f, P = 0.f;
    #pragma unroll
    for (int i = 0; i < 16; i++) {
        float e = __expf(rec[i].x - gM);
        S += e;
        P = fmaf(rec[i].y, e, P);
    }
    S += __shfl_xor_sync(0xffffffffu, S, 1);
    P += __shfl_xor_sync(0xffffffffu, P, 1);
    S += __shfl_xor_sync(0xffffffffu, S, 2);
    P += __shfl_xor_sync(0xffffffffu, P, 2);
    S += __shfl_xor_sync(0xffffffffu, S, 4);
    P += __shfl_xor_sync(0xffffffffu, P, 4);

    if (q == 0)
        out[(size_t)b * NN + n] = P / S;
}

// ---------------------------------------------------------------------------
extern "C" void kernel_launch(void* const* d_in, const int* in_sizes, int n_in,
                              void* d_out, int out_size)
{
    const float* data    = (const float*)d_in[0];   // (64, 256, 64)
    const float* targets = (const float*)d_in[1];   // (64, 256)
    const float* W       = (const float*)d_in[2];   // (4096, 64, 1)
    float* out = (float*)d_out;                     // (64, 256)

    cudaFuncSetAttribute(main_kernel,
                         cudaFuncAttributeMaxDynamicSharedMemorySize,
                         SMEM_BYTES);

    prep_kernel<<<(DATA_ELTS + W_ELTS) / 4096, 256>>>(data, W);
    main_kernel<<<dim3(TCH, BB), THREADS, SMEM_BYTES>>>(targets);
    merge_kernel<<<512, 256>>>(out);
}

// round 16
// speedup vs baseline: 1.2764x; 1.2764x over previous
#include <cuda_runtime.h>
#include <cuda_fp16.h>
#include <math.h>
#include <stdint.h>

#define BB 64
#define NN 256
#define DD 64
#define TT 4096
#define T_TILE 128
#define TCH (TT / T_TILE)          // 32
#define THREADS 128
#define WARPS 4
#define NSLAB 32
#define SLABS (NN / NSLAB)         // 8
#define KREC 32                    // one record per (b, n, tc)

#define DATA_ELTS (BB * NN * DD)   // 1048576
#define W_ELTS (TT * DD)           // 262144

// fp16 limb arrays (hi, mid), row-major d-contiguous
__device__ __align__(16) __half g_dlimb[2][DATA_ELTS];
__device__ __align__(16) __half g_wlimb[2][W_ELTS];
// per-(b, n, tc) LSE records: (lse, r). 4 MB, tc-contiguous for merge.
__device__ float2 g_rec[(size_t)BB * NN * KREC];

// ---- smem layout (per CTA, ~100 KB -> 2 CTAs/SM) ----
// [0, 32768):   W limbs initially; after afrag load, data slabs 0-3
// [32768,65536): data slabs 4-7 (slab s @ s*8192; limb0 +0, limb1 +4096)
#define SM_Z   65536                   // 32 x 132 floats
#define ZSTR   132
#define SM_CV  82432                   // 32 x 132 floats
#define SM_TGT 99328                   // 256 f32
#define SM_REC 100352                  // 3 arrays of 32x5 f32 (stride 5)
#define RECSTR 5
#define SMEM_BYTES (SM_REC + 3 * 32 * RECSTR * 4)   // 102272

static __device__ __forceinline__ uint32_t smem_u32(const void* p) {
    uint32_t a;
    asm("{ .reg .u64 t; cvta.to.shared.u64 t, %1; cvt.u32.u64 %0, t; }"
        : "=r"(a) : "l"(p));
    return a;
}
static __device__ __forceinline__ void cp16(uint32_t dst, const void* src) {
    asm volatile("cp.async.cg.shared.global [%0], [%1], 16;" :: "r"(dst), "l"(src));
}
#define CP_COMMIT() asm volatile("cp.async.commit_group;")
#define CP_WAIT0()  asm volatile("cp.async.wait_group 0;" ::: "memory")

static __device__ __forceinline__ void ldsm4(uint32_t a, uint32_t r[4]) {
    asm volatile("ldmatrix.sync.aligned.m8n8.x4.shared.b16 {%0,%1,%2,%3}, [%4];"
                 : "=r"(r[0]), "=r"(r[1]), "=r"(r[2]), "=r"(r[3]) : "r"(a));
}
static __device__ __forceinline__ void mma_f32(
    float d[4], const uint32_t a[4], uint32_t b0, uint32_t b1) {
    asm volatile(
        "mma.sync.aligned.m16n8k16.row.col.f32.f16.f16.f32 "
        "{%0,%1,%2,%3}, {%4,%5,%6,%7}, {%8,%9}, {%0,%1,%2,%3};"
        : "+f"(d[0]), "+f"(d[1]), "+f"(d[2]), "+f"(d[3])
        : "r"(a[0]), "r"(a[1]), "r"(a[2]), "r"(a[3]), "r"(b0), "r"(b1));
}
static __device__ __forceinline__ void mma_f16(
    uint32_t d[2], const uint32_t a[4], uint32_t b0, uint32_t b1) {
    asm volatile(
        "mma.sync.aligned.m16n8k16.row.col.f16.f16.f16.f16 "
        "{%0,%1}, {%2,%3,%4,%5}, {%6,%7}, {%0,%1};"
        : "+r"(d[0]), "+r"(d[1])
        : "r"(a[0]), "r"(a[1]), "r"(a[2]), "r"(a[3]), "r"(b0), "r"(b1));
}

// ---------------------------------------------------------------------------
// Prep: fp32 -> 2 fp16 limbs (hi/mid), 8 elements per thread. (R14 version)
// ---------------------------------------------------------------------------
__global__ void __launch_bounds__(256)
prep_kernel(const float* __restrict__ data, const float* __restrict__ W)
{
    size_t i = ((size_t)blockIdx.x * 256 + threadIdx.x) * 8;
    const bool isW = (i >= DATA_ELTS);
    size_t j = isW ? i - DATA_ELTS : i;
    const float* src = isW ? (W + j) : (data + j);
    float4 x0 = *(const float4*)src;
    float4 x1 = *(const float4*)(src + 4);

    float v[8] = {x0.x, x0.y, x0.z, x0.w, x1.x, x1.y, x1.z, x1.w};
    uint32_t hp[4], mp[4];
    #pragma unroll
    for (int e = 0; e < 4; e++) {
        __half h0 = __float2half_rn(v[2*e]);
        __half h1 = __float2half_rn(v[2*e+1]);
        __half m0 = __float2half_rn(v[2*e]   - __half2float(h0));
        __half m1 = __float2half_rn(v[2*e+1] - __half2float(h1));
        __half2 hh = __halves2half2(h0, h1);
        __half2 mm = __halves2half2(m0, m1);
        hp[e] = *(uint32_t*)&hh;
        mp[e] = *(uint32_t*)&mm;
    }
    uint4 hv = make_uint4(hp[0], hp[1], hp[2], hp[3]);
    uint4 mv = make_uint4(mp[0], mp[1], mp[2], mp[3]);
    if (isW) {
        *(uint4*)(&g_wlimb[0][j]) = hv;
        *(uint4*)(&g_wlimb[1][j]) = mv;
    } else {
        *(uint4*)(&g_dlimb[0][j]) = hv;
        *(uint4*)(&g_dlimb[1][j]) = mv;
    }
}

// ---------------------------------------------------------------------------
// Main: R14 base (2 CTAs/SM, full residency, fp16 limbs hh-f32 + hm/mh-f16)
// + block-level LSE combine of the 4 warp partials (KREC=32).
// grid (TCH, BB), 128 threads.
// ---------------------------------------------------------------------------
extern "C" __global__ void __launch_bounds__(THREADS, 2)
main_kernel(const float* __restrict__ targets)
{
    extern __shared__ __align__(1024) char smem[];
    const uint32_t sb = smem_u32(smem);
    const int tc   = blockIdx.x;
    const int b    = blockIdx.y;
    const int tid  = threadIdx.x;
    const int w    = tid >> 5;
    const int lane = tid & 31;

    const __half* dbase0 = &g_dlimb[0][(size_t)b * NN * DD];
    const __half* dbase1 = &g_dlimb[1][(size_t)b * NN * DD];

    // ---- phase 1: W limbs (32 KB @0), targets, slabs 4..7 (@32768) ----
    #pragma unroll
    for (int kq = 0; kq < 16; kq++) {
        int i = kq * THREADS + tid;
        int limb = i >> 10, rem = i & 1023, row = rem >> 3, c = rem & 7;
        cp16(sb + limb * 16384 + row * 128 + ((c ^ (row & 7)) << 4),
             &g_wlimb[limb][(size_t)(tc * T_TILE + row) * DD + c * 8]);
    }
    if (tid < 64) cp16(sb + SM_TGT + tid * 16, targets + (size_t)b * NN + tid * 4);
    #pragma unroll
    for (int kq = 0; kq < 16; kq++) {
        int i = kq * THREADS + tid;
        int slab = 4 + (i >> 9);
        int rem  = i & 511;
        int limb = rem >> 8, r2 = rem & 255, row = r2 >> 3, c = r2 & 7;
        const __half* src = limb ? dbase1 : dbase0;
        cp16(sb + slab * 8192 + limb * 4096 + row * 128 + ((c ^ (row & 7)) << 4),
             src + (size_t)(slab * NSLAB + row) * DD + c * 8);
    }
    CP_COMMIT();
    CP_WAIT0();
    __syncthreads();

    // fragment lane decomposition
    const int l7 = lane & 7;
    const int t1 = (lane >> 3) & 1;
    const int t2 = lane >> 4;

    uint32_t xA[4], xB[4];
    #pragma unroll
    for (int k = 0; k < 4; k++) {
        xA[k] = (uint32_t)(((2 * k + t2) ^ l7) << 4);
        xB[k] = (uint32_t)(((2 * k + t1) ^ l7) << 4);
    }

    // ---- load A fragments ONCE from the W region ----
    uint32_t afrag[2][4][2][4];               // [limb][k][half][4]
    {
        const uint32_t aRow = sb + (uint32_t)(32 * w + 8 * t1 + l7) * 128;
        #pragma unroll
        for (int limb = 0; limb < 2; limb++)
            #pragma unroll
            for (int k = 0; k < 4; k++) {
                const uint32_t aL = aRow + (uint32_t)limb * 16384;
                ldsm4(aL + xA[k],        afrag[limb][k][0]);
                ldsm4(aL + 2048 + xA[k], afrag[limb][k][1]);
            }
    }
    __syncthreads();                          // all warps done reading W

    // ---- phase 2: slabs 0..3 into the freed W region (@0) ----
    #pragma unroll
    for (int kq = 0; kq < 16; kq++) {
        int i = kq * THREADS + tid;
        int slab = i >> 9;
        int rem  = i & 511;
        int limb = rem >> 8, r2 = rem & 255, row = r2 >> 3, c = r2 & 7;
        const __half* src = limb ? dbase1 : dbase0;
        cp16(sb + slab * 8192 + limb * 4096 + row * 128 + ((c ^ (row & 7)) << 4),
             src + (size_t)(slab * NSLAB + row) * DD + c * 8);
    }
    CP_COMMIT();
    CP_WAIT0();
    __syncthreads();

    float* zw  = (float*)(smem + SM_Z);
    float* cvw = (float*)(smem + SM_CV);
    const float* s_tgt = (const float*)(smem + SM_TGT);
    float* recM = (float*)(smem + SM_REC);
    float* recS = recM + 32 * RECSTR;
    float* recP = recS + 32 * RECSTR;

    float cum = 0.f;
    const uint32_t bOff = sb + (uint32_t)(8 * t2 + l7) * 128;

    const int r0 = lane >> 2;
    const int c0 = 2 * (lane & 3);

    for (int s = 0; s < SLABS; s++) {
        // ---- load B fragments for slab s ----
        uint32_t bfrag[2][4][2][4];
        const uint32_t bR = bOff + (uint32_t)(s * 8192);
        #pragma unroll
        for (int limb = 0; limb < 2; limb++)
            #pragma unroll
            for (int k = 0; k < 4; k++) {
                const uint32_t bL = bR + (uint32_t)limb * 4096;
                ldsm4(bL + xB[k],        bfrag[limb][k][0]);
                ldsm4(bL + 2048 + xB[k], bfrag[limb][k][1]);
            }

        // ---- GEMM: hh (f32 acc) + hm + mh (f16 acc) ----
        float acc[2][4][4];
        uint32_t accc[2][4][2];
        #pragma unroll
        for (int mt = 0; mt < 2; mt++)
            #pragma unroll
            for (int q = 0; q < 4; q++) {
                acc[mt][q][0] = acc[mt][q][1] = 0.f;
                acc[mt][q][2] = acc[mt][q][3] = 0.f;
                accc[mt][q][0] = 0u; accc[mt][q][1] = 0u;
            }

        #pragma unroll
        for (int k = 0; k < 4; k++) {
            const uint32_t* ah0 = afrag[0][k][0];
            const uint32_t* ah1 = afrag[0][k][1];
            const uint32_t* am0 = afrag[1][k][0];
            const uint32_t* am1 = afrag[1][k][1];
            const uint32_t* bh0 = bfrag[0][k][0];
            const uint32_t* bh1 = bfrag[0][k][1];
            const uint32_t* bm0 = bfrag[1][k][0];
            const uint32_t* bm1 = bfrag[1][k][1];

            mma_f32(acc[0][0], ah0, bh0[0], bh0[1]);
            mma_f32(acc[0][1], ah0, bh0[2], bh0[3]);
            mma_f32(acc[0][2], ah0, bh1[0], bh1[1]);
            mma_f32(acc[0][3], ah0, bh1[2], bh1[3]);
            mma_f32(acc[1][0], ah1, bh0[0], bh0[1]);
            mma_f32(acc[1][1], ah1, bh0[2], bh0[3]);
            mma_f32(acc[1][2], ah1, bh1[0], bh1[1]);
            mma_f32(acc[1][3], ah1, bh1[2], bh1[3]);

            mma_f16(accc[0][0], ah0, bm0[0], bm0[1]);
            mma_f16(accc[0][1], ah0, bm0[2], bm0[3]);
            mma_f16(accc[0][2], ah0, bm1[0], bm1[1]);
            mma_f16(accc[0][3], ah0, bm1[2], bm1[3]);
            mma_f16(accc[1][0], ah1, bm0[0], bm0[1]);
            mma_f16(accc[1][1], ah1, bm0[2], bm0[3]);
            mma_f16(accc[1][2], ah1, bm1[0], bm1[1]);
            mma_f16(accc[1][3], ah1, bm1[2], bm1[3]);

            mma_f16(accc[0][0], am0, bh0[0], bh0[1]);
            mma_f16(accc[0][1], am0, bh0[2], bh0[3]);
            mma_f16(accc[0][2], am0, bh1[0], bh1[1]);
            mma_f16(accc[0][3], am0, bh1[2], bh1[3]);
            mma_f16(accc[1][0], am1, bh0[0], bh0[1]);
            mma_f16(accc[1][1], am1, bh0[2], bh0[3]);
            mma_f16(accc[1][2], am1, bh1[0], bh1[1]);
            mma_f16(accc[1][3], am1, bh1[2], bh1[3]);
        }

        // ---- transpose-store z with f16 corrections folded in ----
        #pragma unroll
        for (int mt = 0; mt < 2; mt++) {
            const int tg = 32 * w + 16 * mt + r0;
            #pragma unroll
            for (int q = 0; q < 4; q++) {
                const int nl = 8 * q + c0;
                __half2 p0 = *reinterpret_cast<__half2*>(&accc[mt][q][0]);
                __half2 p1 = *reinterpret_cast<__half2*>(&accc[mt][q][1]);
                zw[nl * ZSTR + tg]           = acc[mt][q][0] + __low2float(p0);
                zw[(nl + 1) * ZSTR + tg]     = acc[mt][q][1] + __high2float(p0);
                zw[nl * ZSTR + tg + 8]       = acc[mt][q][2] + __low2float(p1);
                zw[(nl + 1) * ZSTR + tg + 8] = acc[mt][q][3] + __high2float(p1);
            }
        }
        __syncwarp();

        // ---- phase A: cumulative loglik scan (thread = task) ----
        #pragma unroll
        for (int j = 0; j < NSLAB; j++) {
            float z  = zw[j * ZSTR + tid];
            float tn = s_tgt[s * NSLAB + j];
            cvw[j * ZSTR + tid] = cum;
            float r = tn - z;
            cum = fmaf(-0.5f * r, r, cum);
        }
        __syncwarp();

        // ---- phase B: per-n in-lane reduction over this warp's 32 tasks ----
        {
            const float* cvr = cvw + lane * ZSTR + 32 * w;
            const float* zr  = zw  + lane * ZSTR + 32 * w;

            float m = -3.4e38f;
            #pragma unroll
            for (int k = 0; k < 8; k++) {
                float4 v = *(const float4*)(cvr + 4 * k);
                m = fmaxf(m, fmaxf(fmaxf(v.x, v.y), fmaxf(v.z, v.w)));
            }
            float S = 0.f, P = 0.f;
            #pragma unroll
            for (int k = 0; k < 8; k++) {
                float4 cv = *(const float4*)(cvr + 4 * k);
                float4 zv = *(const float4*)(zr  + 4 * k);
                float e0 = __expf(cv.x - m);
                float e1 = __expf(cv.y - m);
                float e2 = __expf(cv.z - m);
                float e3 = __expf(cv.w - m);
                S += (e0 + e1) + (e2 + e3);
                P = fmaf(e0, zv.x, P);
                P = fmaf(e1, zv.y, P);
                P = fmaf(e2, zv.z, P);
                P = fmaf(e3, zv.w, P);
            }
            // stash warp partial (lane = n_local)
            recM[lane * RECSTR + w] = m;
            recS[lane * RECSTR + w] = S;
            recP[lane * RECSTR + w] = P;
        }
        __syncthreads();

        // ---- block LSE combine: 4 warp partials -> 1 record per n ----
        if (w == 0) {
            const int n_local = lane;
            float m0 = recM[n_local * RECSTR + 0];
            float m1 = recM[n_local * RECSTR + 1];
            float m2 = recM[n_local * RECSTR + 2];
            float m3 = recM[n_local * RECSTR + 3];
            float gM = fmaxf(fmaxf(m0, m1), fmaxf(m2, m3));
            float e0 = __expf(m0 - gM), e1 = __expf(m1 - gM);
            float e2 = __expf(m2 - gM), e3 = __expf(m3 - gM);
            float S = recS[n_local * RECSTR + 0] * e0
                    + recS[n_local * RECSTR + 1] * e1
                    + recS[n_local * RECSTR + 2] * e2
                    + recS[n_local * RECSTR + 3] * e3;
            float P = recP[n_local * RECSTR + 0] * e0
                    + recP[n_local * RECSTR + 1] * e1
                    + recP[n_local * RECSTR + 2] * e2
                    + recP[n_local * RECSTR + 3] * e3;
            const int n = s * NSLAB + n_local;
            g_rec[((size_t)b * NN + n) * KREC + tc] =
                make_float2(gM + __logf(S), __fdividef(P, S));
        }
        __syncthreads();   // rec arrays + zw/cvw free for next slab
    }
}

// ---------------------------------------------------------------------------
// Merge: 4 threads per (b,n), 8 LSE records each, coalesced tc-major reads.
// n==0 falls out naturally (all partials uniform -> pred0).
// ---------------------------------------------------------------------------
extern "C" __global__ void __launch_bounds__(256)
merge_kernel(float* __restrict__ out)
{
    const int gp = blockIdx.x * 64 + (threadIdx.x >> 2);
    const int q  = threadIdx.x & 3;
    const int b  = gp >> 8;
    const int n  = gp & 255;
    const float2* base = &g_rec[((size_t)b * NN + n) * KREC];

    float2 rec[8];
    float M = -3.4e38f;
    #pragma unroll
    for (int i = 0; i < 8; i++) {
        rec[i] = __ldg(&base[i * 4 + q]);
        M = fmaxf(M, rec[i].x);
    }
    float gM = M;
    gM = fmaxf(gM, __shfl_xor_sync(0xffffffffu, gM, 1));
    gM = fmaxf(gM, __shfl_xor_sync(0xffffffffu, gM, 2));

    float S = 0.f, P = 0.f;
    #pragma unroll
    for (int i = 0; i < 8; i++) {
        float e = __expf(rec[i].x - gM);
        S += e;
        P = fmaf(rec[i].y, e, P);
    }
    S += __shfl_xor_sync(0xffffffffu, S, 1);
    P += __shfl_xor_sync(0xffffffffu, P, 1);
    S += __shfl_xor_sync(0xffffffffu, S, 2);
    P += __shfl_xor_sync(0xffffffffu, P, 2);

    if (q == 0)
        out[(size_t)b * NN + n] = P / S;
}

// ---------------------------------------------------------------------------
extern "C" void kernel_launch(void* const* d_in, const int* in_sizes, int n_in,
                              void* d_out, int out_size)
{
    const float* data    = (const float*)d_in[0];   // (64, 256, 64)
    const float* targets = (const float*)d_in[1];   // (64, 256)
    const float* W       = (const float*)d_in[2];   // (4096, 64, 1)
    float* out = (float*)d_out;                     // (64, 256)

    cudaFuncSetAttribute(main_kernel,
                         cudaFuncAttributeMaxDynamicSharedMemorySize,
                         SMEM_BYTES);

    prep_kernel<<<(DATA_ELTS + W_ELTS) / 2048, 256>>>(data, W);
    main_kernel<<<dim3(TCH, BB), THREADS, SMEM_BYTES>>>(targets);
    merge_kernel<<<256, 256>>>(out);
}